// round 4
// baseline (speedup 1.0000x reference)
#include <cuda_runtime.h>
#include <cstdint>
#include <cstddef>

// Problem dims (fixed by the dataset)
#define B_   16
#define N_   4096
#define S_   1024
#define C1_  256
#define C2_  256
#define K0_  512      // C1+C2
#define M0_  256
#define M1_  256
#define MTOT (B_*N_)  // 65536 rows (b*N+n)

// ---------------- scratch (static device globals; no cudaMalloc allowed) ----
__device__ float g_XT[(size_t)MTOT * K0_];        // [B*N, 512]  concat activations
__device__ float g_p2t[(size_t)B_ * S_ * C2_];    // [B, S, C2]  transposed points2
__device__ int   g_idx[(size_t)B_ * N_ * 3];
__device__ float g_w[(size_t)B_ * N_ * 3];
__device__ float g_y0[(size_t)MTOT * M0_];        // [B*N, 256] layer-0 pre/post BN (in place)
__device__ float g_y1[(size_t)MTOT * M1_];        // [B*N, 256] layer-1 pre-BN
__device__ float g_sum0[M0_], g_sq0[M0_], g_sum1[M1_], g_sq1[M1_];
__device__ float g_scale0[M0_], g_shift0[M0_], g_scale1[M1_], g_shift1[M1_];

// ---------------- packed f32x2 helpers (FFMA2 pipe) -------------------------
static __device__ __forceinline__ unsigned long long pk2(float lo, float hi) {
    unsigned long long r;
    asm("mov.b64 %0, {%1, %2};" : "=l"(r) : "f"(lo), "f"(hi));
    return r;
}
static __device__ __forceinline__ unsigned long long fma2(unsigned long long a,
                                                          unsigned long long b,
                                                          unsigned long long c) {
    unsigned long long d;
    asm("fma.rn.f32x2 %0, %1, %2, %3;" : "=l"(d) : "l"(a), "l"(b), "l"(c));
    return d;
}
static __device__ __forceinline__ void upk2(unsigned long long v, float& lo, float& hi) {
    asm("mov.b64 {%0, %1}, %2;" : "=f"(lo), "=f"(hi) : "l"(v));
}

// ---------------- kernel: zero BN-stat accumulators -------------------------
__global__ void zero_stats_kernel() {
    int t = threadIdx.x;          // 256 threads
    g_sum0[t] = 0.f; g_sq0[t] = 0.f;
    g_sum1[t] = 0.f; g_sq1[t] = 0.f;
}

// ---------------- kernel: transpose points1 [B,C1,N] -> XT[:, 0:256] --------
__global__ void transpose_p1_kernel(const float* __restrict__ p1) {
    __shared__ float tile[32][33];
    int b = blockIdx.z;
    int n0 = blockIdx.x * 32, c0 = blockIdx.y * 32;
    int tx = threadIdx.x, ty = threadIdx.y;
    const float* ip = p1 + (size_t)b * C1_ * N_;
    float* op = g_XT + (size_t)b * N_ * K0_;
#pragma unroll
    for (int i = 0; i < 4; i++) {
        int r = ty + i * 8;
        tile[r][tx] = ip[(size_t)(c0 + r) * N_ + n0 + tx];
    }
    __syncthreads();
#pragma unroll
    for (int i = 0; i < 4; i++) {
        int r = ty + i * 8;
        op[(size_t)(n0 + r) * K0_ + c0 + tx] = tile[tx][r];
    }
}

// ---------------- kernel: transpose points2 [B,C2,S] -> p2t [B,S,C2] --------
__global__ void transpose_p2_kernel(const float* __restrict__ p2) {
    __shared__ float tile[32][33];
    int b = blockIdx.z;
    int s0 = blockIdx.x * 32, c0 = blockIdx.y * 32;
    int tx = threadIdx.x, ty = threadIdx.y;
    const float* ip = p2 + (size_t)b * C2_ * S_;
    float* op = g_p2t + (size_t)b * S_ * C2_;
#pragma unroll
    for (int i = 0; i < 4; i++) {
        int r = ty + i * 8;
        tile[r][tx] = ip[(size_t)(c0 + r) * S_ + s0 + tx];
    }
    __syncthreads();
#pragma unroll
    for (int i = 0; i < 4; i++) {
        int r = ty + i * 8;
        op[(size_t)(s0 + r) * C2_ + c0 + tx] = tile[tx][r];
    }
}

// ---------------- kernel: 3-NN + inverse-distance weights -------------------
__global__ void knn_kernel(const float* __restrict__ xyz1,
                           const float* __restrict__ xyz2) {
    __shared__ float sx[S_], sy[S_], sz[S_], s2[S_];
    int b = blockIdx.y;
    const float* x2 = xyz2 + (size_t)b * 3 * S_;
    for (int j = threadIdx.x; j < S_; j += 128) {
        float a = x2[j], c = x2[S_ + j], d = x2[2 * S_ + j];
        sx[j] = a; sy[j] = c; sz[j] = d;
        s2[j] = a * a + c * c + d * d;
    }
    __syncthreads();

    int n = blockIdx.x * 128 + threadIdx.x;
    const float* x1 = xyz1 + (size_t)b * 3 * N_;
    float px = x1[n], py = x1[N_ + n], pz = x1[2 * N_ + n];
    float n1 = px * px + py * py + pz * pz;

    float d0 = 1e30f, d1 = 1e30f, d2 = 1e30f;
    int i0 = 0, i1 = 0, i2 = 0;
#pragma unroll 4
    for (int s = 0; s < S_; s++) {
        float dot = px * sx[s] + py * sy[s] + pz * sz[s];
        float d = n1 + s2[s] - 2.f * dot;   // same formula as reference
        if (d < d2) {
            if (d < d1) {
                d2 = d1; i2 = i1;
                if (d < d0) { d1 = d0; i1 = i0; d0 = d; i0 = s; }
                else        { d1 = d;  i1 = s; }
            } else { d2 = d; i2 = s; }
        }
    }
    float r0 = 1.f / (d0 + 1e-8f);
    float r1 = 1.f / (d1 + 1e-8f);
    float r2 = 1.f / (d2 + 1e-8f);
    float rs = r0 + r1 + r2;
    size_t base = ((size_t)b * N_ + n) * 3;
    g_idx[base] = i0; g_idx[base + 1] = i1; g_idx[base + 2] = i2;
    g_w[base] = r0 / rs; g_w[base + 1] = r1 / rs; g_w[base + 2] = r2 / rs;
}

// ---------------- kernel: weighted gather -> XT[:, 256:512] -----------------
// One warp per point n; coalesced float4 row reads from p2t (L2-resident).
__global__ void gather_kernel() {
    int b = blockIdx.y;
    int warp = threadIdx.x >> 5, lane = threadIdx.x & 31;
    int n = blockIdx.x * 8 + warp;
    size_t base = ((size_t)b * N_ + n) * 3;
    int i0 = g_idx[base], i1 = g_idx[base + 1], i2 = g_idx[base + 2];
    float w0 = g_w[base], w1 = g_w[base + 1], w2 = g_w[base + 2];
    const float4* r0 = (const float4*)(g_p2t + ((size_t)b * S_ + i0) * C2_);
    const float4* r1 = (const float4*)(g_p2t + ((size_t)b * S_ + i1) * C2_);
    const float4* r2 = (const float4*)(g_p2t + ((size_t)b * S_ + i2) * C2_);
    float4* dst = (float4*)(g_XT + ((size_t)b * N_ + n) * K0_ + C1_);
#pragma unroll
    for (int t = 0; t < 2; t++) {
        int c = lane + t * 32;                 // 64 float4 per 256-ch row
        float4 a = r0[c], bb = r1[c], cc = r2[c];
        float4 o;
        o.x = w0 * a.x + w1 * bb.x + w2 * cc.x;
        o.y = w0 * a.y + w1 * bb.y + w2 * cc.y;
        o.z = w0 * a.z + w1 * bb.z + w2 * cc.z;
        o.w = w0 * a.w + w1 * bb.w + w2 * cc.w;
        dst[c] = o;
    }
}

// ---------------- NT GEMM body: C[M,256] = A[M,K] * Bw[256,K]^T + bias ------
// Also accumulates per-output-channel sum / sumsq (BN training stats).
template <int KDIM>
static __device__ __forceinline__ void gemm_body(const float* __restrict__ A,
                                                 const float* __restrict__ Bw,
                                                 const float* __restrict__ bias,
                                                 float* __restrict__ C,
                                                 float* __restrict__ gsum,
                                                 float* __restrict__ gsq) {
    const int BK = 16;
    __shared__ float As[BK][128];
    __shared__ float Bs[BK][128];

    int m0 = blockIdx.x * 128;
    int n0 = blockIdx.y * 128;
    int tid = threadIdx.x;
    int tx = tid & 15, ty = tid >> 4;

    unsigned long long acc[8][4];
#pragma unroll
    for (int i = 0; i < 8; i++)
#pragma unroll
        for (int j = 0; j < 4; j++) acc[i][j] = 0ull;

    for (int kt = 0; kt < KDIM; kt += BK) {
#pragma unroll
        for (int h = 0; h < 2; h++) {
            int f = tid + h * 256;            // float4 id 0..511
            int row = f >> 2;
            int kc = (f & 3) * 4;
            float4 v = *(const float4*)(A + (size_t)(m0 + row) * KDIM + kt + kc);
            As[kc + 0][row] = v.x; As[kc + 1][row] = v.y;
            As[kc + 2][row] = v.z; As[kc + 3][row] = v.w;
            float4 u = *(const float4*)(Bw + (size_t)(n0 + row) * KDIM + kt + kc);
            Bs[kc + 0][row] = u.x; Bs[kc + 1][row] = u.y;
            Bs[kc + 2][row] = u.z; Bs[kc + 3][row] = u.w;
        }
        __syncthreads();
#pragma unroll
        for (int k = 0; k < BK; k++) {
            float4 a0 = *(const float4*)&As[k][ty * 8];
            float4 a1 = *(const float4*)&As[k][ty * 8 + 4];
            float4 b0 = *(const float4*)&Bs[k][tx * 8];
            float4 b1 = *(const float4*)&Bs[k][tx * 8 + 4];
            unsigned long long bp[4];
            bp[0] = pk2(b0.x, b0.y); bp[1] = pk2(b0.z, b0.w);
            bp[2] = pk2(b1.x, b1.y); bp[3] = pk2(b1.z, b1.w);
            float av[8] = {a0.x, a0.y, a0.z, a0.w, a1.x, a1.y, a1.z, a1.w};
#pragma unroll
            for (int i = 0; i < 8; i++) {
                unsigned long long aa = pk2(av[i], av[i]);
#pragma unroll
                for (int j = 0; j < 4; j++) acc[i][j] = fma2(aa, bp[j], acc[i][j]);
            }
        }
        __syncthreads();
    }

    // ---- epilogue: bias, store, per-channel stats ----
    float bv[8];
#pragma unroll
    for (int j = 0; j < 8; j++) bv[j] = bias[n0 + tx * 8 + j];

    float colsum[8], colsq[8];
#pragma unroll
    for (int j = 0; j < 8; j++) { colsum[j] = 0.f; colsq[j] = 0.f; }

#pragma unroll
    for (int i = 0; i < 8; i++) {
        float v[8];
#pragma unroll
        for (int j = 0; j < 4; j++) upk2(acc[i][j], v[2 * j], v[2 * j + 1]);
#pragma unroll
        for (int j = 0; j < 8; j++) {
            v[j] += bv[j];
            colsum[j] += v[j];
            colsq[j] += v[j] * v[j];
        }
        float4* out = (float4*)(C + (size_t)(m0 + ty * 8 + i) * 256 + n0 + tx * 8);
        out[0] = make_float4(v[0], v[1], v[2], v[3]);
        out[1] = make_float4(v[4], v[5], v[6], v[7]);
    }

    __syncthreads();                     // done with As as GEMM tiles
    float* ssum = &As[0][0];             // reuse smem: 128 + 128 floats
    float* ssq  = &As[0][0] + 128;
    if (tid < 128) { ssum[tid] = 0.f; ssq[tid] = 0.f; }
    __syncthreads();
#pragma unroll
    for (int j = 0; j < 8; j++) {
        atomicAdd(&ssum[tx * 8 + j], colsum[j]);
        atomicAdd(&ssq[tx * 8 + j], colsq[j]);
    }
    __syncthreads();
    if (tid < 128) {
        atomicAdd(&gsum[n0 + tid], ssum[tid]);
        atomicAdd(&gsq[n0 + tid], ssq[tid]);
    }
}

__global__ __launch_bounds__(256, 2)
void gemm1_kernel(const float* __restrict__ w0, const float* __restrict__ b0) {
    gemm_body<K0_>(g_XT, w0, b0, g_y0, g_sum0, g_sq0);
}
__global__ __launch_bounds__(256, 2)
void gemm2_kernel(const float* __restrict__ w1, const float* __restrict__ b1) {
    gemm_body<M0_>(g_y0, w1, b1, g_y1, g_sum1, g_sq1);
}

// ---------------- kernel: finalize BN stats -> scale/shift ------------------
__global__ void finalize0_kernel(const float* __restrict__ gamma,
                                 const float* __restrict__ beta) {
    int c = threadIdx.x;
    float cnt = (float)MTOT;
    float mean = g_sum0[c] / cnt;
    float var = g_sq0[c] / cnt - mean * mean;
    float inv = rsqrtf(var + 1e-5f);
    float sc = gamma[c] * inv;
    g_scale0[c] = sc;
    g_shift0[c] = beta[c] - mean * sc;
}
__global__ void finalize1_kernel(const float* __restrict__ gamma,
                                 const float* __restrict__ beta) {
    int c = threadIdx.x;
    float cnt = (float)MTOT;
    float mean = g_sum1[c] / cnt;
    float var = g_sq1[c] / cnt - mean * mean;
    float inv = rsqrtf(var + 1e-5f);
    float sc = gamma[c] * inv;
    g_scale1[c] = sc;
    g_shift1[c] = beta[c] - mean * sc;
}

// ---------------- kernel: BN + ReLU in place on g_y0 (layer 0) --------------
__global__ void bnrelu0_kernel() {
    size_t i4 = (size_t)blockIdx.x * 256 + threadIdx.x;   // float4 index
    float4* p = (float4*)g_y0;
    float4 v = p[i4];
    int c = ((int)(i4 & 63)) * 4;                          // 64 float4 per 256-ch row
    v.x = fmaxf(v.x * g_scale0[c + 0] + g_shift0[c + 0], 0.f);
    v.y = fmaxf(v.y * g_scale0[c + 1] + g_shift0[c + 1], 0.f);
    v.z = fmaxf(v.z * g_scale0[c + 2] + g_shift0[c + 2], 0.f);
    v.w = fmaxf(v.w * g_scale0[c + 3] + g_shift0[c + 3], 0.f);
    p[i4] = v;
}

// ---------------- kernel: BN + ReLU + transpose -> out [B, M1, N] -----------
__global__ void bnrelu1_transpose_kernel(float* __restrict__ out) {
    __shared__ float tile[32][33];
    int b = blockIdx.z;
    int n0 = blockIdx.x * 32, o0 = blockIdx.y * 32;
    int tx = threadIdx.x, ty = threadIdx.y;
    float sc = g_scale1[o0 + tx];
    float sh = g_shift1[o0 + tx];
    const float* ip = g_y1 + (size_t)b * N_ * M1_;
#pragma unroll
    for (int i = 0; i < 4; i++) {
        int r = ty + i * 8;
        float v = ip[(size_t)(n0 + r) * M1_ + o0 + tx];
        tile[r][tx] = fmaxf(v * sc + sh, 0.f);
    }
    __syncthreads();
    float* op = out + (size_t)b * M1_ * N_;
#pragma unroll
    for (int i = 0; i < 4; i++) {
        int r = ty + i * 8;
        op[(size_t)(o0 + r) * N_ + n0 + tx] = tile[tx][r];
    }
}

// ---------------- launch --------------------------------------------------
extern "C" void kernel_launch(void* const* d_in, const int* in_sizes, int n_in,
                              void* d_out, int out_size) {
    const float* xyz1 = (const float*)d_in[0];
    const float* xyz2 = (const float*)d_in[1];
    const float* p1   = (const float*)d_in[2];
    const float* p2   = (const float*)d_in[3];
    const float* w0   = (const float*)d_in[4];
    const float* b0   = (const float*)d_in[5];
    const float* g0   = (const float*)d_in[6];
    const float* be0  = (const float*)d_in[7];
    const float* w1   = (const float*)d_in[8];
    const float* b1   = (const float*)d_in[9];
    const float* g1   = (const float*)d_in[10];
    const float* be1  = (const float*)d_in[11];
    float* out = (float*)d_out;

    zero_stats_kernel<<<1, 256>>>();
    transpose_p1_kernel<<<dim3(N_ / 32, C1_ / 32, B_), dim3(32, 8)>>>(p1);
    transpose_p2_kernel<<<dim3(S_ / 32, C2_ / 32, B_), dim3(32, 8)>>>(p2);
    knn_kernel<<<dim3(N_ / 128, B_), 128>>>(xyz1, xyz2);
    gather_kernel<<<dim3(N_ / 8, B_), 256>>>();

    gemm1_kernel<<<dim3(MTOT / 128, M0_ / 128), 256>>>(w0, b0);
    finalize0_kernel<<<1, 256>>>(g0, be0);
    bnrelu0_kernel<<<(unsigned)((size_t)MTOT * M0_ / 4 / 256), 256>>>();

    gemm2_kernel<<<dim3(MTOT / 128, M1_ / 128), 256>>>(w1, b1);
    finalize1_kernel<<<1, 256>>>(g1, be1);
    bnrelu1_transpose_kernel<<<dim3(N_ / 32, M1_ / 32, B_), dim3(32, 8)>>>(out);
}

// round 5
// speedup vs baseline: 1.0525x; 1.0525x over previous
#include <cuda_runtime.h>
#include <cstdint>
#include <cstddef>

// Problem dims (fixed by the dataset)
#define B_   16
#define N_   4096
#define S_   1024
#define C1_  256
#define C2_  256
#define K0_  512      // C1+C2
#define M0_  256
#define M1_  256
#define MTOT (B_*N_)  // 65536 rows (b*N+n)

// ---------------- scratch (static device globals; no cudaMalloc allowed) ----
__device__ float g_XT[(size_t)MTOT * K0_];        // [B*N, 512]  concat activations
__device__ float g_p2t[(size_t)B_ * S_ * C2_];    // [B, S, C2]  transposed points2
__device__ int   g_idx[(size_t)B_ * N_ * 3];
__device__ float g_w[(size_t)B_ * N_ * 3];
__device__ float g_y0[(size_t)MTOT * M0_];        // [B*N, 256] layer-0 pre/post BN (in place)
__device__ float g_y1[(size_t)MTOT * M1_];        // [B*N, 256] layer-1 pre-BN
__device__ float g_sum0[M0_], g_sq0[M0_], g_sum1[M1_], g_sq1[M1_];
__device__ float g_scale0[M0_], g_shift0[M0_], g_scale1[M1_], g_shift1[M1_];

// ---------------- packed f32x2 helpers (FFMA2 pipe) -------------------------
static __device__ __forceinline__ unsigned long long pk2(float lo, float hi) {
    unsigned long long r;
    asm("mov.b64 %0, {%1, %2};" : "=l"(r) : "f"(lo), "f"(hi));
    return r;
}
static __device__ __forceinline__ unsigned long long fma2(unsigned long long a,
                                                          unsigned long long b,
                                                          unsigned long long c) {
    unsigned long long d;
    asm("fma.rn.f32x2 %0, %1, %2, %3;" : "=l"(d) : "l"(a), "l"(b), "l"(c));
    return d;
}
static __device__ __forceinline__ void upk2(unsigned long long v, float& lo, float& hi) {
    asm("mov.b64 {%0, %1}, %2;" : "=f"(lo), "=f"(hi) : "l"(v));
}

// ---------------- kernel: zero BN-stat accumulators -------------------------
__global__ void zero_stats_kernel() {
    int t = threadIdx.x;          // 256 threads
    g_sum0[t] = 0.f; g_sq0[t] = 0.f;
    g_sum1[t] = 0.f; g_sq1[t] = 0.f;
}

// ---------------- kernel: transpose points1 [B,C1,N] -> XT[:, 0:256] --------
__global__ void transpose_p1_kernel(const float* __restrict__ p1) {
    __shared__ float tile[32][33];
    int b = blockIdx.z;
    int n0 = blockIdx.x * 32, c0 = blockIdx.y * 32;
    int tx = threadIdx.x, ty = threadIdx.y;
    const float* ip = p1 + (size_t)b * C1_ * N_;
    float* op = g_XT + (size_t)b * N_ * K0_;
#pragma unroll
    for (int i = 0; i < 4; i++) {
        int r = ty + i * 8;
        tile[r][tx] = ip[(size_t)(c0 + r) * N_ + n0 + tx];
    }
    __syncthreads();
#pragma unroll
    for (int i = 0; i < 4; i++) {
        int r = ty + i * 8;
        op[(size_t)(n0 + r) * K0_ + c0 + tx] = tile[tx][r];
    }
}

// ---------------- kernel: transpose points2 [B,C2,S] -> p2t [B,S,C2] --------
__global__ void transpose_p2_kernel(const float* __restrict__ p2) {
    __shared__ float tile[32][33];
    int b = blockIdx.z;
    int s0 = blockIdx.x * 32, c0 = blockIdx.y * 32;
    int tx = threadIdx.x, ty = threadIdx.y;
    const float* ip = p2 + (size_t)b * C2_ * S_;
    float* op = g_p2t + (size_t)b * S_ * C2_;
#pragma unroll
    for (int i = 0; i < 4; i++) {
        int r = ty + i * 8;
        tile[r][tx] = ip[(size_t)(c0 + r) * S_ + s0 + tx];
    }
    __syncthreads();
#pragma unroll
    for (int i = 0; i < 4; i++) {
        int r = ty + i * 8;
        op[(size_t)(s0 + r) * C2_ + c0 + tx] = tile[tx][r];
    }
}

// ---------------- kernel: 3-NN + inverse-distance weights -------------------
__global__ void knn_kernel(const float* __restrict__ xyz1,
                           const float* __restrict__ xyz2) {
    __shared__ float sx[S_], sy[S_], sz[S_], s2[S_];
    int b = blockIdx.y;
    const float* x2 = xyz2 + (size_t)b * 3 * S_;
    for (int j = threadIdx.x; j < S_; j += 128) {
        float a = x2[j], c = x2[S_ + j], d = x2[2 * S_ + j];
        sx[j] = a; sy[j] = c; sz[j] = d;
        s2[j] = a * a + c * c + d * d;
    }
    __syncthreads();

    int n = blockIdx.x * 128 + threadIdx.x;
    const float* x1 = xyz1 + (size_t)b * 3 * N_;
    float px = x1[n], py = x1[N_ + n], pz = x1[2 * N_ + n];
    float n1 = px * px + py * py + pz * pz;

    float d0 = 1e30f, d1 = 1e30f, d2 = 1e30f;
    int i0 = 0, i1 = 0, i2 = 0;
#pragma unroll 4
    for (int s = 0; s < S_; s++) {
        float dot = px * sx[s] + py * sy[s] + pz * sz[s];
        float d = n1 + s2[s] - 2.f * dot;   // same formula as reference
        if (d < d2) {
            if (d < d1) {
                d2 = d1; i2 = i1;
                if (d < d0) { d1 = d0; i1 = i0; d0 = d; i0 = s; }
                else        { d1 = d;  i1 = s; }
            } else { d2 = d; i2 = s; }
        }
    }
    float r0 = 1.f / (d0 + 1e-8f);
    float r1 = 1.f / (d1 + 1e-8f);
    float r2 = 1.f / (d2 + 1e-8f);
    float rs = r0 + r1 + r2;
    size_t base = ((size_t)b * N_ + n) * 3;
    g_idx[base] = i0; g_idx[base + 1] = i1; g_idx[base + 2] = i2;
    g_w[base] = r0 / rs; g_w[base + 1] = r1 / rs; g_w[base + 2] = r2 / rs;
}

// ---------------- kernel: weighted gather -> XT[:, 256:512] -----------------
// One warp per point n; coalesced float4 row reads from p2t (L2-resident).
__global__ void gather_kernel() {
    int b = blockIdx.y;
    int warp = threadIdx.x >> 5, lane = threadIdx.x & 31;
    int n = blockIdx.x * 8 + warp;
    size_t base = ((size_t)b * N_ + n) * 3;
    int i0 = g_idx[base], i1 = g_idx[base + 1], i2 = g_idx[base + 2];
    float w0 = g_w[base], w1 = g_w[base + 1], w2 = g_w[base + 2];
    const float4* r0 = (const float4*)(g_p2t + ((size_t)b * S_ + i0) * C2_);
    const float4* r1 = (const float4*)(g_p2t + ((size_t)b * S_ + i1) * C2_);
    const float4* r2 = (const float4*)(g_p2t + ((size_t)b * S_ + i2) * C2_);
    float4* dst = (float4*)(g_XT + ((size_t)b * N_ + n) * K0_ + C1_);
#pragma unroll
    for (int t = 0; t < 2; t++) {
        int c = lane + t * 32;                 // 64 float4 per 256-ch row
        float4 a = r0[c], bb = r1[c], cc = r2[c];
        float4 o;
        o.x = w0 * a.x + w1 * bb.x + w2 * cc.x;
        o.y = w0 * a.y + w1 * bb.y + w2 * cc.y;
        o.z = w0 * a.z + w1 * bb.z + w2 * cc.z;
        o.w = w0 * a.w + w1 * bb.w + w2 * cc.w;
        dst[c] = o;
    }
}

// ---------------- NT GEMM body: C[M,256] = A[M,K] * Bw[256,K]^T + bias ------
// Also accumulates per-output-channel sum / sumsq (BN training stats).
template <int KDIM>
static __device__ __forceinline__ void gemm_body(const float* __restrict__ A,
                                                 const float* __restrict__ Bw,
                                                 const float* __restrict__ bias,
                                                 float* __restrict__ C,
                                                 float* __restrict__ gsum,
                                                 float* __restrict__ gsq) {
    const int BK = 16;
    __shared__ float As[BK][128];
    __shared__ float Bs[BK][128];

    int m0 = blockIdx.x * 128;
    int n0 = blockIdx.y * 128;
    int tid = threadIdx.x;
    int tx = tid & 15, ty = tid >> 4;

    unsigned long long acc[8][4];
#pragma unroll
    for (int i = 0; i < 8; i++)
#pragma unroll
        for (int j = 0; j < 4; j++) acc[i][j] = 0ull;

    for (int kt = 0; kt < KDIM; kt += BK) {
#pragma unroll
        for (int h = 0; h < 2; h++) {
            int f = tid + h * 256;            // float4 id 0..511
            int row = f >> 2;
            int kc = (f & 3) * 4;
            float4 v = *(const float4*)(A + (size_t)(m0 + row) * KDIM + kt + kc);
            As[kc + 0][row] = v.x; As[kc + 1][row] = v.y;
            As[kc + 2][row] = v.z; As[kc + 3][row] = v.w;
            float4 u = *(const float4*)(Bw + (size_t)(n0 + row) * KDIM + kt + kc);
            Bs[kc + 0][row] = u.x; Bs[kc + 1][row] = u.y;
            Bs[kc + 2][row] = u.z; Bs[kc + 3][row] = u.w;
        }
        __syncthreads();
#pragma unroll
        for (int k = 0; k < BK; k++) {
            float4 a0 = *(const float4*)&As[k][ty * 8];
            float4 a1 = *(const float4*)&As[k][ty * 8 + 4];
            float4 b0 = *(const float4*)&Bs[k][tx * 8];
            float4 b1 = *(const float4*)&Bs[k][tx * 8 + 4];
            unsigned long long bp[4];
            bp[0] = pk2(b0.x, b0.y); bp[1] = pk2(b0.z, b0.w);
            bp[2] = pk2(b1.x, b1.y); bp[3] = pk2(b1.z, b1.w);
            float av[8] = {a0.x, a0.y, a0.z, a0.w, a1.x, a1.y, a1.z, a1.w};
#pragma unroll
            for (int i = 0; i < 8; i++) {
                unsigned long long aa = pk2(av[i], av[i]);
#pragma unroll
                for (int j = 0; j < 4; j++) acc[i][j] = fma2(aa, bp[j], acc[i][j]);
            }
        }
        __syncthreads();
    }

    // ---- epilogue: bias, store, per-channel stats ----
    float bv[8];
#pragma unroll
    for (int j = 0; j < 8; j++) bv[j] = bias[n0 + tx * 8 + j];

    float colsum[8], colsq[8];
#pragma unroll
    for (int j = 0; j < 8; j++) { colsum[j] = 0.f; colsq[j] = 0.f; }

#pragma unroll
    for (int i = 0; i < 8; i++) {
        float v[8];
#pragma unroll
        for (int j = 0; j < 4; j++) upk2(acc[i][j], v[2 * j], v[2 * j + 1]);
#pragma unroll
        for (int j = 0; j < 8; j++) {
            v[j] += bv[j];
            colsum[j] += v[j];
            colsq[j] += v[j] * v[j];
        }
        float4* out = (float4*)(C + (size_t)(m0 + ty * 8 + i) * 256 + n0 + tx * 8);
        out[0] = make_float4(v[0], v[1], v[2], v[3]);
        out[1] = make_float4(v[4], v[5], v[6], v[7]);
    }

    __syncthreads();                     // done with As as GEMM tiles
    float* ssum = &As[0][0];             // reuse smem: 128 + 128 floats
    float* ssq  = &As[0][0] + 128;
    if (tid < 128) { ssum[tid] = 0.f; ssq[tid] = 0.f; }
    __syncthreads();
#pragma unroll
    for (int j = 0; j < 8; j++) {
        atomicAdd(&ssum[tx * 8 + j], colsum[j]);
        atomicAdd(&ssq[tx * 8 + j], colsq[j]);
    }
    __syncthreads();
    if (tid < 128) {
        atomicAdd(&gsum[n0 + tid], ssum[tid]);
        atomicAdd(&gsq[n0 + tid], ssq[tid]);
    }
}

__global__ __launch_bounds__(256, 2)
void gemm1_kernel(const float* __restrict__ w0, const float* __restrict__ b0) {
    gemm_body<K0_>(g_XT, w0, b0, g_y0, g_sum0, g_sq0);
}
__global__ __launch_bounds__(256, 2)
void gemm2_kernel(const float* __restrict__ w1, const float* __restrict__ b1) {
    gemm_body<M0_>(g_y0, w1, b1, g_y1, g_sum1, g_sq1);
}

// ---------------- kernel: finalize BN stats -> scale/shift ------------------
__global__ void finalize0_kernel(const float* __restrict__ gamma,
                                 const float* __restrict__ beta) {
    int c = threadIdx.x;
    float cnt = (float)MTOT;
    float mean = g_sum0[c] / cnt;
    float var = g_sq0[c] / cnt - mean * mean;
    float inv = rsqrtf(var + 1e-5f);
    float sc = gamma[c] * inv;
    g_scale0[c] = sc;
    g_shift0[c] = beta[c] - mean * sc;
}
__global__ void finalize1_kernel(const float* __restrict__ gamma,
                                 const float* __restrict__ beta) {
    int c = threadIdx.x;
    float cnt = (float)MTOT;
    float mean = g_sum1[c] / cnt;
    float var = g_sq1[c] / cnt - mean * mean;
    float inv = rsqrtf(var + 1e-5f);
    float sc = gamma[c] * inv;
    g_scale1[c] = sc;
    g_shift1[c] = beta[c] - mean * sc;
}

// ---------------- kernel: BN + ReLU in place on g_y0 (layer 0) --------------
__global__ void bnrelu0_kernel() {
    size_t i4 = (size_t)blockIdx.x * 256 + threadIdx.x;   // float4 index
    float4* p = (float4*)g_y0;
    float4 v = p[i4];
    int c = ((int)(i4 & 63)) * 4;                          // 64 float4 per 256-ch row
    v.x = fmaxf(v.x * g_scale0[c + 0] + g_shift0[c + 0], 0.f);
    v.y = fmaxf(v.y * g_scale0[c + 1] + g_shift0[c + 1], 0.f);
    v.z = fmaxf(v.z * g_scale0[c + 2] + g_shift0[c + 2], 0.f);
    v.w = fmaxf(v.w * g_scale0[c + 3] + g_shift0[c + 3], 0.f);
    p[i4] = v;
}

// ---------------- kernel: BN + ReLU + transpose -> out [B, M1, N] -----------
__global__ void bnrelu1_transpose_kernel(float* __restrict__ out) {
    __shared__ float tile[32][33];
    int b = blockIdx.z;
    int n0 = blockIdx.x * 32, o0 = blockIdx.y * 32;
    int tx = threadIdx.x, ty = threadIdx.y;
    float sc = g_scale1[o0 + tx];
    float sh = g_shift1[o0 + tx];
    const float* ip = g_y1 + (size_t)b * N_ * M1_;
#pragma unroll
    for (int i = 0; i < 4; i++) {
        int r = ty + i * 8;
        float v = ip[(size_t)(n0 + r) * M1_ + o0 + tx];
        tile[r][tx] = fmaxf(v * sc + sh, 0.f);
    }
    __syncthreads();
    float* op = out + (size_t)b * M1_ * N_;
#pragma unroll
    for (int i = 0; i < 4; i++) {
        int r = ty + i * 8;
        op[(size_t)(o0 + r) * N_ + n0 + tx] = tile[tx][r];
    }
}

// ---------------- launch --------------------------------------------------
extern "C" void kernel_launch(void* const* d_in, const int* in_sizes, int n_in,
                              void* d_out, int out_size) {
    const float* xyz1 = (const float*)d_in[0];
    const float* xyz2 = (const float*)d_in[1];
    const float* p1   = (const float*)d_in[2];
    const float* p2   = (const float*)d_in[3];
    const float* w0   = (const float*)d_in[4];
    const float* b0   = (const float*)d_in[5];
    const float* g0   = (const float*)d_in[6];
    const float* be0  = (const float*)d_in[7];
    const float* w1   = (const float*)d_in[8];
    const float* b1   = (const float*)d_in[9];
    const float* g1   = (const float*)d_in[10];
    const float* be1  = (const float*)d_in[11];
    float* out = (float*)d_out;

    zero_stats_kernel<<<1, 256>>>();
    transpose_p1_kernel<<<dim3(N_ / 32, C1_ / 32, B_), dim3(32, 8)>>>(p1);
    transpose_p2_kernel<<<dim3(S_ / 32, C2_ / 32, B_), dim3(32, 8)>>>(p2);
    knn_kernel<<<dim3(N_ / 128, B_), 128>>>(xyz1, xyz2);
    gather_kernel<<<dim3(N_ / 8, B_), 256>>>();

    gemm1_kernel<<<dim3(MTOT / 128, M0_ / 128), 256>>>(w0, b0);
    finalize0_kernel<<<1, 256>>>(g0, be0);
    bnrelu0_kernel<<<(unsigned)((size_t)MTOT * M0_ / 4 / 256), 256>>>();

    gemm2_kernel<<<dim3(MTOT / 128, M1_ / 128), 256>>>(w1, b1);
    finalize1_kernel<<<1, 256>>>(g1, be1);
    bnrelu1_transpose_kernel<<<dim3(N_ / 32, M1_ / 32, B_), dim3(32, 8)>>>(out);
}

// round 6
// speedup vs baseline: 1.0535x; 1.0010x over previous
#include <cuda_runtime.h>
#include <cstdint>
#include <cstddef>

// Problem dims (fixed by the dataset)
#define B_   16
#define N_   4096
#define S_   1024
#define C1_  256
#define C2_  256
#define K0_  512      // C1+C2
#define M0_  256
#define M1_  256
#define MTOT (B_*N_)  // 65536 rows (b*N+n)

// ---------------- scratch (static device globals; no cudaMalloc allowed) ----
__device__ float g_XT[(size_t)MTOT * K0_];        // [B*N, 512]  concat activations
__device__ float g_p2t[(size_t)B_ * S_ * C2_];    // [B, S, C2]  transposed points2
__device__ int   g_idx[(size_t)B_ * N_ * 3];
__device__ float g_w[(size_t)B_ * N_ * 3];
__device__ float g_y0[(size_t)MTOT * M0_];        // [B*N, 256] layer-0 pre/post BN (in place)
__device__ float g_y1[(size_t)MTOT * M1_];        // [B*N, 256] layer-1 pre-BN
__device__ float g_sum0[M0_], g_sq0[M0_], g_sum1[M1_], g_sq1[M1_];
__device__ float g_scale0[M0_], g_shift0[M0_], g_scale1[M1_], g_shift1[M1_];

// ---------------- packed f32x2 helpers (FFMA2 pipe) -------------------------
static __device__ __forceinline__ unsigned long long pk2(float lo, float hi) {
    unsigned long long r;
    asm("mov.b64 %0, {%1, %2};" : "=l"(r) : "f"(lo), "f"(hi));
    return r;
}
static __device__ __forceinline__ unsigned long long fma2(unsigned long long a,
                                                          unsigned long long b,
                                                          unsigned long long c) {
    unsigned long long d;
    asm("fma.rn.f32x2 %0, %1, %2, %3;" : "=l"(d) : "l"(a), "l"(b), "l"(c));
    return d;
}
static __device__ __forceinline__ void upk2(unsigned long long v, float& lo, float& hi) {
    asm("mov.b64 {%0, %1}, %2;" : "=f"(lo), "=f"(hi) : "l"(v));
}

// ---------------- kernel: zero BN-stat accumulators -------------------------
__global__ void zero_stats_kernel() {
    int t = threadIdx.x;          // 256 threads
    g_sum0[t] = 0.f; g_sq0[t] = 0.f;
    g_sum1[t] = 0.f; g_sq1[t] = 0.f;
}

// ---------------- kernel: transpose points1 [B,C1,N] -> XT[:, 0:256] --------
__global__ void transpose_p1_kernel(const float* __restrict__ p1) {
    __shared__ float tile[32][33];
    int b = blockIdx.z;
    int n0 = blockIdx.x * 32, c0 = blockIdx.y * 32;
    int tx = threadIdx.x, ty = threadIdx.y;
    const float* ip = p1 + (size_t)b * C1_ * N_;
    float* op = g_XT + (size_t)b * N_ * K0_;
#pragma unroll
    for (int i = 0; i < 4; i++) {
        int r = ty + i * 8;
        tile[r][tx] = ip[(size_t)(c0 + r) * N_ + n0 + tx];
    }
    __syncthreads();
#pragma unroll
    for (int i = 0; i < 4; i++) {
        int r = ty + i * 8;
        op[(size_t)(n0 + r) * K0_ + c0 + tx] = tile[tx][r];
    }
}

// ---------------- kernel: transpose points2 [B,C2,S] -> p2t [B,S,C2] --------
__global__ void transpose_p2_kernel(const float* __restrict__ p2) {
    __shared__ float tile[32][33];
    int b = blockIdx.z;
    int s0 = blockIdx.x * 32, c0 = blockIdx.y * 32;
    int tx = threadIdx.x, ty = threadIdx.y;
    const float* ip = p2 + (size_t)b * C2_ * S_;
    float* op = g_p2t + (size_t)b * S_ * C2_;
#pragma unroll
    for (int i = 0; i < 4; i++) {
        int r = ty + i * 8;
        tile[r][tx] = ip[(size_t)(c0 + r) * S_ + s0 + tx];
    }
    __syncthreads();
#pragma unroll
    for (int i = 0; i < 4; i++) {
        int r = ty + i * 8;
        op[(size_t)(s0 + r) * C2_ + c0 + tx] = tile[tx][r];
    }
}

// ---------------- kernel: 3-NN + inverse-distance weights -------------------
__global__ void knn_kernel(const float* __restrict__ xyz1,
                           const float* __restrict__ xyz2) {
    __shared__ float sx[S_], sy[S_], sz[S_], s2[S_];
    int b = blockIdx.y;
    const float* x2 = xyz2 + (size_t)b * 3 * S_;
    for (int j = threadIdx.x; j < S_; j += 128) {
        float a = x2[j], c = x2[S_ + j], d = x2[2 * S_ + j];
        sx[j] = a; sy[j] = c; sz[j] = d;
        s2[j] = a * a + c * c + d * d;
    }
    __syncthreads();

    int n = blockIdx.x * 128 + threadIdx.x;
    const float* x1 = xyz1 + (size_t)b * 3 * N_;
    float px = x1[n], py = x1[N_ + n], pz = x1[2 * N_ + n];
    float n1 = px * px + py * py + pz * pz;

    float d0 = 1e30f, d1 = 1e30f, d2 = 1e30f;
    int i0 = 0, i1 = 0, i2 = 0;
#pragma unroll 4
    for (int s = 0; s < S_; s++) {
        float dot = px * sx[s] + py * sy[s] + pz * sz[s];
        float d = n1 + s2[s] - 2.f * dot;   // same formula as reference
        if (d < d2) {
            if (d < d1) {
                d2 = d1; i2 = i1;
                if (d < d0) { d1 = d0; i1 = i0; d0 = d; i0 = s; }
                else        { d1 = d;  i1 = s; }
            } else { d2 = d; i2 = s; }
        }
    }
    float r0 = 1.f / (d0 + 1e-8f);
    float r1 = 1.f / (d1 + 1e-8f);
    float r2 = 1.f / (d2 + 1e-8f);
    float rs = r0 + r1 + r2;
    size_t base = ((size_t)b * N_ + n) * 3;
    g_idx[base] = i0; g_idx[base + 1] = i1; g_idx[base + 2] = i2;
    g_w[base] = r0 / rs; g_w[base + 1] = r1 / rs; g_w[base + 2] = r2 / rs;
}

// ---------------- kernel: weighted gather -> XT[:, 256:512] -----------------
// One warp per point n; coalesced float4 row reads from p2t (L2-resident).
__global__ void gather_kernel() {
    int b = blockIdx.y;
    int warp = threadIdx.x >> 5, lane = threadIdx.x & 31;
    int n = blockIdx.x * 8 + warp;
    size_t base = ((size_t)b * N_ + n) * 3;
    int i0 = g_idx[base], i1 = g_idx[base + 1], i2 = g_idx[base + 2];
    float w0 = g_w[base], w1 = g_w[base + 1], w2 = g_w[base + 2];
    const float4* r0 = (const float4*)(g_p2t + ((size_t)b * S_ + i0) * C2_);
    const float4* r1 = (const float4*)(g_p2t + ((size_t)b * S_ + i1) * C2_);
    const float4* r2 = (const float4*)(g_p2t + ((size_t)b * S_ + i2) * C2_);
    float4* dst = (float4*)(g_XT + ((size_t)b * N_ + n) * K0_ + C1_);
#pragma unroll
    for (int t = 0; t < 2; t++) {
        int c = lane + t * 32;                 // 64 float4 per 256-ch row
        float4 a = r0[c], bb = r1[c], cc = r2[c];
        float4 o;
        o.x = w0 * a.x + w1 * bb.x + w2 * cc.x;
        o.y = w0 * a.y + w1 * bb.y + w2 * cc.y;
        o.z = w0 * a.z + w1 * bb.z + w2 * cc.z;
        o.w = w0 * a.w + w1 * bb.w + w2 * cc.w;
        dst[c] = o;
    }
}

// ---------------- NT GEMM body: C[M,256] = A[M,K] * Bw[256,K]^T + bias ------
// Also accumulates per-output-channel sum / sumsq (BN training stats).
template <int KDIM>
static __device__ __forceinline__ void gemm_body(const float* __restrict__ A,
                                                 const float* __restrict__ Bw,
                                                 const float* __restrict__ bias,
                                                 float* __restrict__ C,
                                                 float* __restrict__ gsum,
                                                 float* __restrict__ gsq) {
    const int BK = 16;
    __shared__ float As[BK][128];
    __shared__ float Bs[BK][128];

    int m0 = blockIdx.x * 128;
    int n0 = blockIdx.y * 128;
    int tid = threadIdx.x;
    int tx = tid & 15, ty = tid >> 4;

    unsigned long long acc[8][4];
#pragma unroll
    for (int i = 0; i < 8; i++)
#pragma unroll
        for (int j = 0; j < 4; j++) acc[i][j] = 0ull;

    for (int kt = 0; kt < KDIM; kt += BK) {
#pragma unroll
        for (int h = 0; h < 2; h++) {
            int f = tid + h * 256;            // float4 id 0..511
            int row = f >> 2;
            int kc = (f & 3) * 4;
            float4 v = *(const float4*)(A + (size_t)(m0 + row) * KDIM + kt + kc);
            As[kc + 0][row] = v.x; As[kc + 1][row] = v.y;
            As[kc + 2][row] = v.z; As[kc + 3][row] = v.w;
            float4 u = *(const float4*)(Bw + (size_t)(n0 + row) * KDIM + kt + kc);
            Bs[kc + 0][row] = u.x; Bs[kc + 1][row] = u.y;
            Bs[kc + 2][row] = u.z; Bs[kc + 3][row] = u.w;
        }
        __syncthreads();
#pragma unroll
        for (int k = 0; k < BK; k++) {
            float4 a0 = *(const float4*)&As[k][ty * 8];
            float4 a1 = *(const float4*)&As[k][ty * 8 + 4];
            float4 b0 = *(const float4*)&Bs[k][tx * 8];
            float4 b1 = *(const float4*)&Bs[k][tx * 8 + 4];
            unsigned long long bp[4];
            bp[0] = pk2(b0.x, b0.y); bp[1] = pk2(b0.z, b0.w);
            bp[2] = pk2(b1.x, b1.y); bp[3] = pk2(b1.z, b1.w);
            float av[8] = {a0.x, a0.y, a0.z, a0.w, a1.x, a1.y, a1.z, a1.w};
#pragma unroll
            for (int i = 0; i < 8; i++) {
                unsigned long long aa = pk2(av[i], av[i]);
#pragma unroll
                for (int j = 0; j < 4; j++) acc[i][j] = fma2(aa, bp[j], acc[i][j]);
            }
        }
        __syncthreads();
    }

    // ---- epilogue: bias, store, per-channel stats ----
    float bv[8];
#pragma unroll
    for (int j = 0; j < 8; j++) bv[j] = bias[n0 + tx * 8 + j];

    float colsum[8], colsq[8];
#pragma unroll
    for (int j = 0; j < 8; j++) { colsum[j] = 0.f; colsq[j] = 0.f; }

#pragma unroll
    for (int i = 0; i < 8; i++) {
        float v[8];
#pragma unroll
        for (int j = 0; j < 4; j++) upk2(acc[i][j], v[2 * j], v[2 * j + 1]);
#pragma unroll
        for (int j = 0; j < 8; j++) {
            v[j] += bv[j];
            colsum[j] += v[j];
            colsq[j] += v[j] * v[j];
        }
        float4* out = (float4*)(C + (size_t)(m0 + ty * 8 + i) * 256 + n0 + tx * 8);
        out[0] = make_float4(v[0], v[1], v[2], v[3]);
        out[1] = make_float4(v[4], v[5], v[6], v[7]);
    }

    __syncthreads();                     // done with As as GEMM tiles
    float* ssum = &As[0][0];             // reuse smem: 128 + 128 floats
    float* ssq  = &As[0][0] + 128;
    if (tid < 128) { ssum[tid] = 0.f; ssq[tid] = 0.f; }
    __syncthreads();
#pragma unroll
    for (int j = 0; j < 8; j++) {
        atomicAdd(&ssum[tx * 8 + j], colsum[j]);
        atomicAdd(&ssq[tx * 8 + j], colsq[j]);
    }
    __syncthreads();
    if (tid < 128) {
        atomicAdd(&gsum[n0 + tid], ssum[tid]);
        atomicAdd(&gsq[n0 + tid], ssq[tid]);
    }
}

__global__ __launch_bounds__(256, 2)
void gemm1_kernel(const float* __restrict__ w0, const float* __restrict__ b0) {
    gemm_body<K0_>(g_XT, w0, b0, g_y0, g_sum0, g_sq0);
}
__global__ __launch_bounds__(256, 2)
void gemm2_kernel(const float* __restrict__ w1, const float* __restrict__ b1) {
    gemm_body<M0_>(g_y0, w1, b1, g_y1, g_sum1, g_sq1);
}

// ---------------- kernel: finalize BN stats -> scale/shift ------------------
__global__ void finalize0_kernel(const float* __restrict__ gamma,
                                 const float* __restrict__ beta) {
    int c = threadIdx.x;
    float cnt = (float)MTOT;
    float mean = g_sum0[c] / cnt;
    float var = g_sq0[c] / cnt - mean * mean;
    float inv = rsqrtf(var + 1e-5f);
    float sc = gamma[c] * inv;
    g_scale0[c] = sc;
    g_shift0[c] = beta[c] - mean * sc;
}
__global__ void finalize1_kernel(const float* __restrict__ gamma,
                                 const float* __restrict__ beta) {
    int c = threadIdx.x;
    float cnt = (float)MTOT;
    float mean = g_sum1[c] / cnt;
    float var = g_sq1[c] / cnt - mean * mean;
    float inv = rsqrtf(var + 1e-5f);
    float sc = gamma[c] * inv;
    g_scale1[c] = sc;
    g_shift1[c] = beta[c] - mean * sc;
}

// ---------------- kernel: BN + ReLU in place on g_y0 (layer 0) --------------
__global__ void bnrelu0_kernel() {
    size_t i4 = (size_t)blockIdx.x * 256 + threadIdx.x;   // float4 index
    float4* p = (float4*)g_y0;
    float4 v = p[i4];
    int c = ((int)(i4 & 63)) * 4;                          // 64 float4 per 256-ch row
    v.x = fmaxf(v.x * g_scale0[c + 0] + g_shift0[c + 0], 0.f);
    v.y = fmaxf(v.y * g_scale0[c + 1] + g_shift0[c + 1], 0.f);
    v.z = fmaxf(v.z * g_scale0[c + 2] + g_shift0[c + 2], 0.f);
    v.w = fmaxf(v.w * g_scale0[c + 3] + g_shift0[c + 3], 0.f);
    p[i4] = v;
}

// ---------------- kernel: BN + ReLU + transpose -> out [B, M1, N] -----------
__global__ void bnrelu1_transpose_kernel(float* __restrict__ out) {
    __shared__ float tile[32][33];
    int b = blockIdx.z;
    int n0 = blockIdx.x * 32, o0 = blockIdx.y * 32;
    int tx = threadIdx.x, ty = threadIdx.y;
    float sc = g_scale1[o0 + tx];
    float sh = g_shift1[o0 + tx];
    const float* ip = g_y1 + (size_t)b * N_ * M1_;
#pragma unroll
    for (int i = 0; i < 4; i++) {
        int r = ty + i * 8;
        float v = ip[(size_t)(n0 + r) * M1_ + o0 + tx];
        tile[r][tx] = fmaxf(v * sc + sh, 0.f);
    }
    __syncthreads();
    float* op = out + (size_t)b * M1_ * N_;
#pragma unroll
    for (int i = 0; i < 4; i++) {
        int r = ty + i * 8;
        op[(size_t)(o0 + r) * N_ + n0 + tx] = tile[tx][r];
    }
}

// ---------------- launch --------------------------------------------------
extern "C" void kernel_launch(void* const* d_in, const int* in_sizes, int n_in,
                              void* d_out, int out_size) {
    const float* xyz1 = (const float*)d_in[0];
    const float* xyz2 = (const float*)d_in[1];
    const float* p1   = (const float*)d_in[2];
    const float* p2   = (const float*)d_in[3];
    const float* w0   = (const float*)d_in[4];
    const float* b0   = (const float*)d_in[5];
    const float* g0   = (const float*)d_in[6];
    const float* be0  = (const float*)d_in[7];
    const float* w1   = (const float*)d_in[8];
    const float* b1   = (const float*)d_in[9];
    const float* g1   = (const float*)d_in[10];
    const float* be1  = (const float*)d_in[11];
    float* out = (float*)d_out;

    zero_stats_kernel<<<1, 256>>>();
    transpose_p1_kernel<<<dim3(N_ / 32, C1_ / 32, B_), dim3(32, 8)>>>(p1);
    transpose_p2_kernel<<<dim3(S_ / 32, C2_ / 32, B_), dim3(32, 8)>>>(p2);
    knn_kernel<<<dim3(N_ / 128, B_), 128>>>(xyz1, xyz2);
    gather_kernel<<<dim3(N_ / 8, B_), 256>>>();

    gemm1_kernel<<<dim3(MTOT / 128, M0_ / 128), 256>>>(w0, b0);
    finalize0_kernel<<<1, 256>>>(g0, be0);
    bnrelu0_kernel<<<(unsigned)((size_t)MTOT * M0_ / 4 / 256), 256>>>();

    gemm2_kernel<<<dim3(MTOT / 128, M1_ / 128), 256>>>(w1, b1);
    finalize1_kernel<<<1, 256>>>(g1, be1);
    bnrelu1_transpose_kernel<<<dim3(N_ / 32, M1_ / 32, B_), dim3(32, 8)>>>(out);
}

// round 7
// speedup vs baseline: 1.0543x; 1.0008x over previous
#include <cuda_runtime.h>
#include <cstdint>
#include <cstddef>

// Problem dims (fixed by the dataset)
#define B_   16
#define N_   4096
#define S_   1024
#define C1_  256
#define C2_  256
#define K0_  512      // C1+C2
#define M0_  256
#define M1_  256
#define MTOT (B_*N_)  // 65536 rows (b*N+n)

// ---------------- scratch (static device globals; no cudaMalloc allowed) ----
__device__ float g_XT[(size_t)MTOT * K0_];        // [B*N, 512]  concat activations
__device__ float g_p2t[(size_t)B_ * S_ * C2_];    // [B, S, C2]  transposed points2
__device__ int   g_idx[(size_t)B_ * N_ * 3];
__device__ float g_w[(size_t)B_ * N_ * 3];
__device__ float g_y0[(size_t)MTOT * M0_];        // [B*N, 256] layer-0 pre/post BN (in place)
__device__ float g_y1[(size_t)MTOT * M1_];        // [B*N, 256] layer-1 pre-BN
__device__ float g_sum0[M0_], g_sq0[M0_], g_sum1[M1_], g_sq1[M1_];
__device__ float g_scale0[M0_], g_shift0[M0_], g_scale1[M1_], g_shift1[M1_];

// ---------------- packed f32x2 helpers (FFMA2 pipe) -------------------------
static __device__ __forceinline__ unsigned long long pk2(float lo, float hi) {
    unsigned long long r;
    asm("mov.b64 %0, {%1, %2};" : "=l"(r) : "f"(lo), "f"(hi));
    return r;
}
static __device__ __forceinline__ unsigned long long fma2(unsigned long long a,
                                                          unsigned long long b,
                                                          unsigned long long c) {
    unsigned long long d;
    asm("fma.rn.f32x2 %0, %1, %2, %3;" : "=l"(d) : "l"(a), "l"(b), "l"(c));
    return d;
}
static __device__ __forceinline__ void upk2(unsigned long long v, float& lo, float& hi) {
    asm("mov.b64 {%0, %1}, %2;" : "=f"(lo), "=f"(hi) : "l"(v));
}

// ---------------- kernel: zero BN-stat accumulators -------------------------
__global__ void zero_stats_kernel() {
    int t = threadIdx.x;          // 256 threads
    g_sum0[t] = 0.f; g_sq0[t] = 0.f;
    g_sum1[t] = 0.f; g_sq1[t] = 0.f;
}

// ---------------- kernel: transpose points1 [B,C1,N] -> XT[:, 0:256] --------
__global__ void transpose_p1_kernel(const float* __restrict__ p1) {
    __shared__ float tile[32][33];
    int b = blockIdx.z;
    int n0 = blockIdx.x * 32, c0 = blockIdx.y * 32;
    int tx = threadIdx.x, ty = threadIdx.y;
    const float* ip = p1 + (size_t)b * C1_ * N_;
    float* op = g_XT + (size_t)b * N_ * K0_;
#pragma unroll
    for (int i = 0; i < 4; i++) {
        int r = ty + i * 8;
        tile[r][tx] = ip[(size_t)(c0 + r) * N_ + n0 + tx];
    }
    __syncthreads();
#pragma unroll
    for (int i = 0; i < 4; i++) {
        int r = ty + i * 8;
        op[(size_t)(n0 + r) * K0_ + c0 + tx] = tile[tx][r];
    }
}

// ---------------- kernel: transpose points2 [B,C2,S] -> p2t [B,S,C2] --------
__global__ void transpose_p2_kernel(const float* __restrict__ p2) {
    __shared__ float tile[32][33];
    int b = blockIdx.z;
    int s0 = blockIdx.x * 32, c0 = blockIdx.y * 32;
    int tx = threadIdx.x, ty = threadIdx.y;
    const float* ip = p2 + (size_t)b * C2_ * S_;
    float* op = g_p2t + (size_t)b * S_ * C2_;
#pragma unroll
    for (int i = 0; i < 4; i++) {
        int r = ty + i * 8;
        tile[r][tx] = ip[(size_t)(c0 + r) * S_ + s0 + tx];
    }
    __syncthreads();
#pragma unroll
    for (int i = 0; i < 4; i++) {
        int r = ty + i * 8;
        op[(size_t)(s0 + r) * C2_ + c0 + tx] = tile[tx][r];
    }
}

// ---------------- kernel: 3-NN + inverse-distance weights -------------------
__global__ void knn_kernel(const float* __restrict__ xyz1,
                           const float* __restrict__ xyz2) {
    __shared__ float sx[S_], sy[S_], sz[S_], s2[S_];
    int b = blockIdx.y;
    const float* x2 = xyz2 + (size_t)b * 3 * S_;
    for (int j = threadIdx.x; j < S_; j += 128) {
        float a = x2[j], c = x2[S_ + j], d = x2[2 * S_ + j];
        sx[j] = a; sy[j] = c; sz[j] = d;
        s2[j] = a * a + c * c + d * d;
    }
    __syncthreads();

    int n = blockIdx.x * 128 + threadIdx.x;
    const float* x1 = xyz1 + (size_t)b * 3 * N_;
    float px = x1[n], py = x1[N_ + n], pz = x1[2 * N_ + n];
    float n1 = px * px + py * py + pz * pz;

    float d0 = 1e30f, d1 = 1e30f, d2 = 1e30f;
    int i0 = 0, i1 = 0, i2 = 0;
#pragma unroll 4
    for (int s = 0; s < S_; s++) {
        float dot = px * sx[s] + py * sy[s] + pz * sz[s];
        float d = n1 + s2[s] - 2.f * dot;   // same formula as reference
        if (d < d2) {
            if (d < d1) {
                d2 = d1; i2 = i1;
                if (d < d0) { d1 = d0; i1 = i0; d0 = d; i0 = s; }
                else        { d1 = d;  i1 = s; }
            } else { d2 = d; i2 = s; }
        }
    }
    float r0 = 1.f / (d0 + 1e-8f);
    float r1 = 1.f / (d1 + 1e-8f);
    float r2 = 1.f / (d2 + 1e-8f);
    float rs = r0 + r1 + r2;
    size_t base = ((size_t)b * N_ + n) * 3;
    g_idx[base] = i0; g_idx[base + 1] = i1; g_idx[base + 2] = i2;
    g_w[base] = r0 / rs; g_w[base + 1] = r1 / rs; g_w[base + 2] = r2 / rs;
}

// ---------------- kernel: weighted gather -> XT[:, 256:512] -----------------
// One warp per point n; coalesced float4 row reads from p2t (L2-resident).
__global__ void gather_kernel() {
    int b = blockIdx.y;
    int warp = threadIdx.x >> 5, lane = threadIdx.x & 31;
    int n = blockIdx.x * 8 + warp;
    size_t base = ((size_t)b * N_ + n) * 3;
    int i0 = g_idx[base], i1 = g_idx[base + 1], i2 = g_idx[base + 2];
    float w0 = g_w[base], w1 = g_w[base + 1], w2 = g_w[base + 2];
    const float4* r0 = (const float4*)(g_p2t + ((size_t)b * S_ + i0) * C2_);
    const float4* r1 = (const float4*)(g_p2t + ((size_t)b * S_ + i1) * C2_);
    const float4* r2 = (const float4*)(g_p2t + ((size_t)b * S_ + i2) * C2_);
    float4* dst = (float4*)(g_XT + ((size_t)b * N_ + n) * K0_ + C1_);
#pragma unroll
    for (int t = 0; t < 2; t++) {
        int c = lane + t * 32;                 // 64 float4 per 256-ch row
        float4 a = r0[c], bb = r1[c], cc = r2[c];
        float4 o;
        o.x = w0 * a.x + w1 * bb.x + w2 * cc.x;
        o.y = w0 * a.y + w1 * bb.y + w2 * cc.y;
        o.z = w0 * a.z + w1 * bb.z + w2 * cc.z;
        o.w = w0 * a.w + w1 * bb.w + w2 * cc.w;
        dst[c] = o;
    }
}

// ---------------- NT GEMM body: C[M,256] = A[M,K] * Bw[256,K]^T + bias ------
// Also accumulates per-output-channel sum / sumsq (BN training stats).
template <int KDIM>
static __device__ __forceinline__ void gemm_body(const float* __restrict__ A,
                                                 const float* __restrict__ Bw,
                                                 const float* __restrict__ bias,
                                                 float* __restrict__ C,
                                                 float* __restrict__ gsum,
                                                 float* __restrict__ gsq) {
    const int BK = 16;
    __shared__ float As[BK][128];
    __shared__ float Bs[BK][128];

    int m0 = blockIdx.x * 128;
    int n0 = blockIdx.y * 128;
    int tid = threadIdx.x;
    int tx = tid & 15, ty = tid >> 4;

    unsigned long long acc[8][4];
#pragma unroll
    for (int i = 0; i < 8; i++)
#pragma unroll
        for (int j = 0; j < 4; j++) acc[i][j] = 0ull;

    for (int kt = 0; kt < KDIM; kt += BK) {
#pragma unroll
        for (int h = 0; h < 2; h++) {
            int f = tid + h * 256;            // float4 id 0..511
            int row = f >> 2;
            int kc = (f & 3) * 4;
            float4 v = *(const float4*)(A + (size_t)(m0 + row) * KDIM + kt + kc);
            As[kc + 0][row] = v.x; As[kc + 1][row] = v.y;
            As[kc + 2][row] = v.z; As[kc + 3][row] = v.w;
            float4 u = *(const float4*)(Bw + (size_t)(n0 + row) * KDIM + kt + kc);
            Bs[kc + 0][row] = u.x; Bs[kc + 1][row] = u.y;
            Bs[kc + 2][row] = u.z; Bs[kc + 3][row] = u.w;
        }
        __syncthreads();
#pragma unroll
        for (int k = 0; k < BK; k++) {
            float4 a0 = *(const float4*)&As[k][ty * 8];
            float4 a1 = *(const float4*)&As[k][ty * 8 + 4];
            float4 b0 = *(const float4*)&Bs[k][tx * 8];
            float4 b1 = *(const float4*)&Bs[k][tx * 8 + 4];
            unsigned long long bp[4];
            bp[0] = pk2(b0.x, b0.y); bp[1] = pk2(b0.z, b0.w);
            bp[2] = pk2(b1.x, b1.y); bp[3] = pk2(b1.z, b1.w);
            float av[8] = {a0.x, a0.y, a0.z, a0.w, a1.x, a1.y, a1.z, a1.w};
#pragma unroll
            for (int i = 0; i < 8; i++) {
                unsigned long long aa = pk2(av[i], av[i]);
#pragma unroll
                for (int j = 0; j < 4; j++) acc[i][j] = fma2(aa, bp[j], acc[i][j]);
            }
        }
        __syncthreads();
    }

    // ---- epilogue: bias, store, per-channel stats ----
    float bv[8];
#pragma unroll
    for (int j = 0; j < 8; j++) bv[j] = bias[n0 + tx * 8 + j];

    float colsum[8], colsq[8];
#pragma unroll
    for (int j = 0; j < 8; j++) { colsum[j] = 0.f; colsq[j] = 0.f; }

#pragma unroll
    for (int i = 0; i < 8; i++) {
        float v[8];
#pragma unroll
        for (int j = 0; j < 4; j++) upk2(acc[i][j], v[2 * j], v[2 * j + 1]);
#pragma unroll
        for (int j = 0; j < 8; j++) {
            v[j] += bv[j];
            colsum[j] += v[j];
            colsq[j] += v[j] * v[j];
        }
        float4* out = (float4*)(C + (size_t)(m0 + ty * 8 + i) * 256 + n0 + tx * 8);
        out[0] = make_float4(v[0], v[1], v[2], v[3]);
        out[1] = make_float4(v[4], v[5], v[6], v[7]);
    }

    __syncthreads();                     // done with As as GEMM tiles
    float* ssum = &As[0][0];             // reuse smem: 128 + 128 floats
    float* ssq  = &As[0][0] + 128;
    if (tid < 128) { ssum[tid] = 0.f; ssq[tid] = 0.f; }
    __syncthreads();
#pragma unroll
    for (int j = 0; j < 8; j++) {
        atomicAdd(&ssum[tx * 8 + j], colsum[j]);
        atomicAdd(&ssq[tx * 8 + j], colsq[j]);
    }
    __syncthreads();
    if (tid < 128) {
        atomicAdd(&gsum[n0 + tid], ssum[tid]);
        atomicAdd(&gsq[n0 + tid], ssq[tid]);
    }
}

__global__ __launch_bounds__(256, 2)
void gemm1_kernel(const float* __restrict__ w0, const float* __restrict__ b0) {
    gemm_body<K0_>(g_XT, w0, b0, g_y0, g_sum0, g_sq0);
}
__global__ __launch_bounds__(256, 2)
void gemm2_kernel(const float* __restrict__ w1, const float* __restrict__ b1) {
    gemm_body<M0_>(g_y0, w1, b1, g_y1, g_sum1, g_sq1);
}

// ---------------- kernel: finalize BN stats -> scale/shift ------------------
__global__ void finalize0_kernel(const float* __restrict__ gamma,
                                 const float* __restrict__ beta) {
    int c = threadIdx.x;
    float cnt = (float)MTOT;
    float mean = g_sum0[c] / cnt;
    float var = g_sq0[c] / cnt - mean * mean;
    float inv = rsqrtf(var + 1e-5f);
    float sc = gamma[c] * inv;
    g_scale0[c] = sc;
    g_shift0[c] = beta[c] - mean * sc;
}
__global__ void finalize1_kernel(const float* __restrict__ gamma,
                                 const float* __restrict__ beta) {
    int c = threadIdx.x;
    float cnt = (float)MTOT;
    float mean = g_sum1[c] / cnt;
    float var = g_sq1[c] / cnt - mean * mean;
    float inv = rsqrtf(var + 1e-5f);
    float sc = gamma[c] * inv;
    g_scale1[c] = sc;
    g_shift1[c] = beta[c] - mean * sc;
}

// ---------------- kernel: BN + ReLU in place on g_y0 (layer 0) --------------
__global__ void bnrelu0_kernel() {
    size_t i4 = (size_t)blockIdx.x * 256 + threadIdx.x;   // float4 index
    float4* p = (float4*)g_y0;
    float4 v = p[i4];
    int c = ((int)(i4 & 63)) * 4;                          // 64 float4 per 256-ch row
    v.x = fmaxf(v.x * g_scale0[c + 0] + g_shift0[c + 0], 0.f);
    v.y = fmaxf(v.y * g_scale0[c + 1] + g_shift0[c + 1], 0.f);
    v.z = fmaxf(v.z * g_scale0[c + 2] + g_shift0[c + 2], 0.f);
    v.w = fmaxf(v.w * g_scale0[c + 3] + g_shift0[c + 3], 0.f);
    p[i4] = v;
}

// ---------------- kernel: BN + ReLU + transpose -> out [B, M1, N] -----------
__global__ void bnrelu1_transpose_kernel(float* __restrict__ out) {
    __shared__ float tile[32][33];
    int b = blockIdx.z;
    int n0 = blockIdx.x * 32, o0 = blockIdx.y * 32;
    int tx = threadIdx.x, ty = threadIdx.y;
    float sc = g_scale1[o0 + tx];
    float sh = g_shift1[o0 + tx];
    const float* ip = g_y1 + (size_t)b * N_ * M1_;
#pragma unroll
    for (int i = 0; i < 4; i++) {
        int r = ty + i * 8;
        float v = ip[(size_t)(n0 + r) * M1_ + o0 + tx];
        tile[r][tx] = fmaxf(v * sc + sh, 0.f);
    }
    __syncthreads();
    float* op = out + (size_t)b * M1_ * N_;
#pragma unroll
    for (int i = 0; i < 4; i++) {
        int r = ty + i * 8;
        op[(size_t)(o0 + r) * N_ + n0 + tx] = tile[tx][r];
    }
}

// ---------------- launch --------------------------------------------------
extern "C" void kernel_launch(void* const* d_in, const int* in_sizes, int n_in,
                              void* d_out, int out_size) {
    const float* xyz1 = (const float*)d_in[0];
    const float* xyz2 = (const float*)d_in[1];
    const float* p1   = (const float*)d_in[2];
    const float* p2   = (const float*)d_in[3];
    const float* w0   = (const float*)d_in[4];
    const float* b0   = (const float*)d_in[5];
    const float* g0   = (const float*)d_in[6];
    const float* be0  = (const float*)d_in[7];
    const float* w1   = (const float*)d_in[8];
    const float* b1   = (const float*)d_in[9];
    const float* g1   = (const float*)d_in[10];
    const float* be1  = (const float*)d_in[11];
    float* out = (float*)d_out;

    zero_stats_kernel<<<1, 256>>>();
    transpose_p1_kernel<<<dim3(N_ / 32, C1_ / 32, B_), dim3(32, 8)>>>(p1);
    transpose_p2_kernel<<<dim3(S_ / 32, C2_ / 32, B_), dim3(32, 8)>>>(p2);
    knn_kernel<<<dim3(N_ / 128, B_), 128>>>(xyz1, xyz2);
    gather_kernel<<<dim3(N_ / 8, B_), 256>>>();

    gemm1_kernel<<<dim3(MTOT / 128, M0_ / 128), 256>>>(w0, b0);
    finalize0_kernel<<<1, 256>>>(g0, be0);
    bnrelu0_kernel<<<(unsigned)((size_t)MTOT * M0_ / 4 / 256), 256>>>();

    gemm2_kernel<<<dim3(MTOT / 128, M1_ / 128), 256>>>(w1, b1);
    finalize1_kernel<<<1, 256>>>(g1, be1);
    bnrelu1_transpose_kernel<<<dim3(N_ / 32, M1_ / 32, B_), dim3(32, 8)>>>(out);
}